// round 1
// baseline (speedup 1.0000x reference)
#include <cuda_runtime.h>
#include <math.h>

// ---------------- problem constants ----------------
#define N_B   2
#define C_IN  1088
#define C_MID 136
#define HW    4096

// scratch: normalized feature maps (per batch): 2*136*4096 floats each
__device__ __align__(16) float g_fa[N_B * C_MID * HW];
__device__ __align__(16) float g_fb[N_B * C_MID * HW];

// ---------------- reductions ----------------
__device__ __forceinline__ float blk_sum(float v, float* red) {
    const int tid = threadIdx.x;
    #pragma unroll
    for (int o = 16; o > 0; o >>= 1) v += __shfl_down_sync(0xffffffffu, v, o);
    if ((tid & 31) == 0) red[tid >> 5] = v;
    __syncthreads();
    if (tid < 32) {
        v = (tid < 8) ? red[tid] : 0.f;
        #pragma unroll
        for (int o = 4; o > 0; o >>= 1) v += __shfl_down_sync(0xffffffffu, v, o);
        if (tid == 0) red[0] = v;
    }
    __syncthreads();
    v = red[0];
    __syncthreads();
    return v;
}

__device__ __forceinline__ float blk_max(float v, float* red) {
    const int tid = threadIdx.x;
    #pragma unroll
    for (int o = 16; o > 0; o >>= 1) v = fmaxf(v, __shfl_down_sync(0xffffffffu, v, o));
    if ((tid & 31) == 0) red[tid >> 5] = v;
    __syncthreads();
    if (tid < 32) {
        v = (tid < 8) ? red[tid] : -3.4e38f;
        #pragma unroll
        for (int o = 4; o > 0; o >>= 1) v = fmaxf(v, __shfl_down_sync(0xffffffffu, v, o));
        if (tid == 0) red[0] = v;
    }
    __syncthreads();
    v = red[0];
    __syncthreads();
    return v;
}

// ---------------- generic tiled SGEMM ----------------
// C[m,n] = sum_k opA[m,k] * B[k,n]  (+bias[m] if EPI==1, *alpha if EPI==2)
// TRANS_A=false: A is [M,K] row-major.   TRANS_A=true: A is [K,M] row-major.
// B always [K,N] row-major. Requires K%8==0, N%128==0 (true for all uses).
#define BM 128
#define BN 128
#define BK 8
#define TM 8
#define TN 8

template<bool TRANS_A, int EPI>
__global__ __launch_bounds__(256, 2)
void sgemm_kernel(const float* __restrict__ A, const float* __restrict__ B,
                  const float* __restrict__ bias, float* __restrict__ C,
                  int M, int N, int K,
                  long sA, long sB, long sC, float alpha)
{
    __shared__ float As[BK][BM];
    __shared__ float Bs[BK][BN];

    A += (long)blockIdx.z * sA;
    B += (long)blockIdx.z * sB;
    C += (long)blockIdx.z * sC;

    const int m0 = blockIdx.y * BM;
    const int n0 = blockIdx.x * BN;
    const int tid = threadIdx.x;
    const int tx = tid & 15;
    const int ty = tid >> 4;
    const int idx = tid * 4;

    float acc[TM][TN];
    #pragma unroll
    for (int i = 0; i < TM; i++)
        #pragma unroll
        for (int j = 0; j < TN; j++) acc[i][j] = 0.f;

    for (int k0 = 0; k0 < K; k0 += BK) {
        if (TRANS_A) {
            // A[K,M]: direct contiguous copy (M multiple of 128 in our uses)
            const int kk = idx / BM;
            const int mm = idx % BM;
            const float4 v = *reinterpret_cast<const float4*>(
                A + (long)(k0 + kk) * M + (m0 + mm));
            *reinterpret_cast<float4*>(&As[kk][mm]) = v;
        } else {
            // A[M,K]: load 4 along K, store transposed
            const int mm = idx / BK;
            const int kk = idx % BK;     // 0 or 4
            const int row = m0 + mm;
            float4 v = make_float4(0.f, 0.f, 0.f, 0.f);
            if (row < M)
                v = *reinterpret_cast<const float4*>(A + (long)row * K + (k0 + kk));
            As[kk + 0][mm] = v.x;
            As[kk + 1][mm] = v.y;
            As[kk + 2][mm] = v.z;
            As[kk + 3][mm] = v.w;
        }
        {
            const int kk = idx / BN;
            const int nn = idx % BN;
            const float4 v = *reinterpret_cast<const float4*>(
                B + (long)(k0 + kk) * N + (n0 + nn));
            *reinterpret_cast<float4*>(&Bs[kk][nn]) = v;
        }
        __syncthreads();

        #pragma unroll
        for (int kk = 0; kk < BK; kk++) {
            float ra[TM], rb[TN];
            #pragma unroll
            for (int i = 0; i < TM; i++) ra[i] = As[kk][ty * TM + i];
            #pragma unroll
            for (int j = 0; j < TN; j++) rb[j] = Bs[kk][tx * TN + j];
            #pragma unroll
            for (int i = 0; i < TM; i++)
                #pragma unroll
                for (int j = 0; j < TN; j++)
                    acc[i][j] += ra[i] * rb[j];
        }
        __syncthreads();
    }

    #pragma unroll
    for (int i = 0; i < TM; i++) {
        const int row = m0 + ty * TM + i;
        if (row >= M) continue;
        const float bv = (EPI == 1) ? bias[row] : 0.f;
        #pragma unroll
        for (int j = 0; j < TN; j += 4) {
            const int col = n0 + tx * TN + j;
            float4 v;
            v.x = acc[i][j + 0]; v.y = acc[i][j + 1];
            v.z = acc[i][j + 2]; v.w = acc[i][j + 3];
            if (EPI == 1) { v.x += bv; v.y += bv; v.z += bv; v.w += bv; }
            if (EPI == 2) { v.x *= alpha; v.y *= alpha; v.z *= alpha; v.w *= alpha; }
            *reinterpret_cast<float4*>(C + (long)row * N + col) = v;
        }
    }
}

// ---------------- instance norm + LeakyReLU + spatial re-center (in place) ----------------
// one block per (channel, batch); row cached in smem
__global__ __launch_bounds__(256)
void instnorm_kernel(float* __restrict__ F)
{
    __shared__ float sh[HW];
    __shared__ float red[8];
    const int c = blockIdx.x;
    const int n = blockIdx.y;
    float* row = F + ((long)n * C_MID + c) * HW;
    const int tid = threadIdx.x;

    float s = 0.f, s2 = 0.f;
    for (int i = tid; i < HW; i += 256) {
        const float v = row[i];
        sh[i] = v; s += v; s2 += v * v;
    }
    s  = blk_sum(s,  red);
    s2 = blk_sum(s2, red);
    const float mean = s * (1.f / HW);
    const float var  = s2 * (1.f / HW) - mean * mean;
    const float inv  = rsqrtf(var + 1e-5f);

    float s3 = 0.f;
    for (int i = tid; i < HW; i += 256) {
        float v = (sh[i] - mean) * inv;
        v = (v >= 0.f) ? v : 0.2f * v;
        sh[i] = v;
        s3 += v;
    }
    s3 = blk_sum(s3, red);
    const float mean2 = s3 * (1.f / HW);
    for (int i = tid; i < HW; i += 256)
        row[i] = sh[i] - mean2;
}

// ---------------- per-spatial-column L2 normalize over channels (in place) ----------------
__global__ __launch_bounds__(256)
void l2norm_kernel(float* __restrict__ F)
{
    const int l = blockIdx.x * 256 + threadIdx.x;
    const int n = blockIdx.y;
    float* base = F + (long)n * C_MID * HW + l;
    float s = 0.f;
    #pragma unroll 8
    for (int c = 0; c < C_MID; c++) {
        const float v = base[(long)c * HW];
        s += v * v;
    }
    const float inv = rsqrtf(s);
    #pragma unroll 8
    for (int c = 0; c < C_MID; c++)
        base[(long)c * HW] *= inv;
}

// ---------------- in-place row softmax ----------------
// one block per row of [2*N_B * HW] rows of length HW
__global__ __launch_bounds__(256)
void softmax_kernel(float* __restrict__ E)
{
    __shared__ float sh[HW];
    __shared__ float red[8];
    float* row = E + ((long)blockIdx.y * HW + blockIdx.x) * HW;
    const int tid = threadIdx.x;

    float mx = -3.4e38f;
    for (int i = tid; i < HW; i += 256) {
        const float v = row[i];
        sh[i] = v;
        mx = fmaxf(mx, v);
    }
    mx = blk_max(mx, red);

    float s = 0.f;
    for (int i = tid; i < HW; i += 256) {
        const float e = __expf(sh[i] - mx);
        sh[i] = e;
        s += e;
    }
    s = blk_sum(s, red);
    const float inv = 1.f / s;
    for (int i = tid; i < HW; i += 256)
        row[i] = sh[i] * inv;
}

// ---------------- launch ----------------
extern "C" void kernel_launch(void* const* d_in, const int* in_sizes, int n_in,
                              void* d_out, int out_size)
{
    const float* fa    = (const float*)d_in[0];
    const float* fb    = (const float*)d_in[1];
    const float* a_raw = (const float*)d_in[2];
    const float* b_raw = (const float*)d_in[3];
    const float* Wa    = (const float*)d_in[4];
    const float* ba    = (const float*)d_in[5];
    const float* Wb    = (const float*)d_in[6];
    const float* bb    = (const float*)d_in[7];
    float* out = (float*)d_out;

    float *pfa, *pfb;
    cudaGetSymbolAddress((void**)&pfa, g_fa);
    cudaGetSymbolAddress((void**)&pfb, g_fb);

    const long CORR = (long)HW * HW;                 // per-batch corr elems
    float* corr_ab = out;                            // [N_B, HW, HW]
    float* corr_ba = out + (long)N_B * CORR;         // [N_B, HW, HW]
    float* a_warp  = out + 2L * N_B * CORR;          // [N_B, C_IN, HW]
    float* b_warp  = a_warp + (long)N_B * C_IN * HW; // [N_B, C_IN, HW]

    const dim3 blk(256);

    // 1) 1x1 conv: g_f = W @ X + bias  (per batch)
    {
        dim3 g(HW / BN, (C_MID + BM - 1) / BM, N_B);
        sgemm_kernel<false, 1><<<g, blk>>>(Wa, fa, ba, pfa, C_MID, HW, C_IN,
                                           0L, (long)C_IN * HW, (long)C_MID * HW, 0.f);
        sgemm_kernel<false, 1><<<g, blk>>>(Wb, fb, bb, pfb, C_MID, HW, C_IN,
                                           0L, (long)C_IN * HW, (long)C_MID * HW, 0.f);
    }

    // 2) InstanceNorm + LeakyReLU + spatial re-center
    {
        dim3 g(C_MID, N_B);
        instnorm_kernel<<<g, blk>>>(pfa);
        instnorm_kernel<<<g, blk>>>(pfb);
    }

    // 3) per-column L2 normalize over channels
    {
        dim3 g(HW / 256, N_B);
        l2norm_kernel<<<g, blk>>>(pfa);
        l2norm_kernel<<<g, blk>>>(pfb);
    }

    // 4) energy GEMMs, written straight into the corr output regions (x100)
    {
        dim3 g(HW / BN, HW / BM, N_B);
        // energy_ab[k,l] = sum_c fb[c,k] * fa[c,l]
        sgemm_kernel<true, 2><<<g, blk>>>(pfb, pfa, nullptr, corr_ab, HW, HW, C_MID,
                                          (long)C_MID * HW, (long)C_MID * HW, CORR, 100.f);
        // energy_ba[k,l] = sum_c fa[c,k] * fb[c,l]
        sgemm_kernel<true, 2><<<g, blk>>>(pfa, pfb, nullptr, corr_ba, HW, HW, C_MID,
                                          (long)C_MID * HW, (long)C_MID * HW, CORR, 100.f);
    }

    // 5) in-place softmax over every row of both corr tensors (2*N_B*HW rows)
    {
        dim3 g(HW, 2 * N_B);
        softmax_kernel<<<g, blk>>>(out);
    }

    // 6) warp GEMMs: warp[c,l] = sum_k raw[c,k] * corr[k,l]
    {
        dim3 g(HW / BN, (C_IN + BM - 1) / BM, N_B);
        sgemm_kernel<false, 0><<<g, blk>>>(b_raw, corr_ab, nullptr, b_warp,
                                           C_IN, HW, HW,
                                           (long)C_IN * HW, CORR, (long)C_IN * HW, 0.f);
        sgemm_kernel<false, 0><<<g, blk>>>(a_raw, corr_ba, nullptr, a_warp,
                                           C_IN, HW, HW,
                                           (long)C_IN * HW, CORR, (long)C_IN * HW, 0.f);
    }
}

// round 2
// speedup vs baseline: 1.1254x; 1.1254x over previous
#include <cuda_runtime.h>
#include <math.h>
#include <stdint.h>

// ---------------- problem constants ----------------
#define N_B   2
#define C_IN  1088
#define C_MID 136
#define HW    4096

// scratch: normalized feature maps (per batch)
__device__ __align__(16) float g_fa[N_B * C_MID * HW];
__device__ __align__(16) float g_fb[N_B * C_MID * HW];

// ---------------- reductions ----------------
__device__ __forceinline__ float blk_sum(float v, float* red) {
    const int tid = threadIdx.x;
    #pragma unroll
    for (int o = 16; o > 0; o >>= 1) v += __shfl_down_sync(0xffffffffu, v, o);
    if ((tid & 31) == 0) red[tid >> 5] = v;
    __syncthreads();
    if (tid < 32) {
        v = (tid < 8) ? red[tid] : 0.f;
        #pragma unroll
        for (int o = 4; o > 0; o >>= 1) v += __shfl_down_sync(0xffffffffu, v, o);
        if (tid == 0) red[0] = v;
    }
    __syncthreads();
    v = red[0];
    __syncthreads();
    return v;
}

__device__ __forceinline__ float blk_max(float v, float* red) {
    const int tid = threadIdx.x;
    #pragma unroll
    for (int o = 16; o > 0; o >>= 1) v = fmaxf(v, __shfl_down_sync(0xffffffffu, v, o));
    if ((tid & 31) == 0) red[tid >> 5] = v;
    __syncthreads();
    if (tid < 32) {
        v = (tid < 8) ? red[tid] : -3.4e38f;
        #pragma unroll
        for (int o = 4; o > 0; o >>= 1) v = fmaxf(v, __shfl_down_sync(0xffffffffu, v, o));
        if (tid == 0) red[0] = v;
    }
    __syncthreads();
    v = red[0];
    __syncthreads();
    return v;
}

// ---------------- generic tiled fp32 SGEMM (conv + energy; precision-critical) ----------------
#define BM 128
#define BN 128
#define BK 8
#define TM 8
#define TN 8

template<bool TRANS_A, int EPI>
__global__ __launch_bounds__(256, 2)
void sgemm_kernel(const float* __restrict__ A, const float* __restrict__ B,
                  const float* __restrict__ bias, float* __restrict__ C,
                  int M, int N, int K,
                  long sA, long sB, long sC, float alpha)
{
    __shared__ float As[BK][BM];
    __shared__ float Bs[BK][BN];

    A += (long)blockIdx.z * sA;
    B += (long)blockIdx.z * sB;
    C += (long)blockIdx.z * sC;

    const int m0 = blockIdx.y * BM;
    const int n0 = blockIdx.x * BN;
    const int tid = threadIdx.x;
    const int tx = tid & 15;
    const int ty = tid >> 4;
    const int idx = tid * 4;

    float acc[TM][TN];
    #pragma unroll
    for (int i = 0; i < TM; i++)
        #pragma unroll
        for (int j = 0; j < TN; j++) acc[i][j] = 0.f;

    for (int k0 = 0; k0 < K; k0 += BK) {
        if (TRANS_A) {
            const int kk = idx / BM;
            const int mm = idx % BM;
            const float4 v = *reinterpret_cast<const float4*>(
                A + (long)(k0 + kk) * M + (m0 + mm));
            *reinterpret_cast<float4*>(&As[kk][mm]) = v;
        } else {
            const int mm = idx / BK;
            const int kk = idx % BK;
            const int row = m0 + mm;
            float4 v = make_float4(0.f, 0.f, 0.f, 0.f);
            if (row < M)
                v = *reinterpret_cast<const float4*>(A + (long)row * K + (k0 + kk));
            As[kk + 0][mm] = v.x;
            As[kk + 1][mm] = v.y;
            As[kk + 2][mm] = v.z;
            As[kk + 3][mm] = v.w;
        }
        {
            const int kk = idx / BN;
            const int nn = idx % BN;
            const float4 v = *reinterpret_cast<const float4*>(
                B + (long)(k0 + kk) * N + (n0 + nn));
            *reinterpret_cast<float4*>(&Bs[kk][nn]) = v;
        }
        __syncthreads();

        #pragma unroll
        for (int kk = 0; kk < BK; kk++) {
            float ra[TM], rb[TN];
            #pragma unroll
            for (int i = 0; i < TM; i++) ra[i] = As[kk][ty * TM + i];
            #pragma unroll
            for (int j = 0; j < TN; j++) rb[j] = Bs[kk][tx * TN + j];
            #pragma unroll
            for (int i = 0; i < TM; i++)
                #pragma unroll
                for (int j = 0; j < TN; j++)
                    acc[i][j] += ra[i] * rb[j];
        }
        __syncthreads();
    }

    #pragma unroll
    for (int i = 0; i < TM; i++) {
        const int row = m0 + ty * TM + i;
        if (row >= M) continue;
        const float bv = (EPI == 1) ? bias[row] : 0.f;
        #pragma unroll
        for (int j = 0; j < TN; j += 4) {
            const int col = n0 + tx * TN + j;
            float4 v;
            v.x = acc[i][j + 0]; v.y = acc[i][j + 1];
            v.z = acc[i][j + 2]; v.w = acc[i][j + 3];
            if (EPI == 1) { v.x += bv; v.y += bv; v.z += bv; v.w += bv; }
            if (EPI == 2) { v.x *= alpha; v.y *= alpha; v.z *= alpha; v.w *= alpha; }
            *reinterpret_cast<float4*>(C + (long)row * N + col) = v;
        }
    }
}

// ---------------- tf32 tensor-core GEMM for the warp stage ----------------
// C[M,4096] = A[M,4096] @ B[4096,4096], all row-major, fp32 in/out, tf32 mma.
// CTA 128x128, 8 warps (2 M x 4 N), warp tile 64x32 of m16n8k8 fragments.
// Loader scatters tf32-converted elements into fragment-ordered smem so the
// consumer reads A fragments with LDS.128 and B fragments with LDS.64.

#define WG_K 4096
#define WG_N 4096
#define WG_NKC (WG_K / 32)

__device__ __forceinline__ float to_tf32(float f) {
    uint32_t u;
    asm("cvt.rna.tf32.f32 %0, %1;" : "=r"(u) : "f"(f));
    return __uint_as_float(u);
}

__device__ __forceinline__ void mma_tf32(float4& c, const uint4& a, const uint2& b) {
    asm volatile(
        "mma.sync.aligned.m16n8k8.row.col.f32.tf32.tf32.f32 "
        "{%0,%1,%2,%3},{%4,%5,%6,%7},{%8,%9},{%0,%1,%2,%3};"
        : "+f"(c.x), "+f"(c.y), "+f"(c.z), "+f"(c.w)
        : "r"(a.x), "r"(a.y), "r"(a.z), "r"(a.w), "r"(b.x), "r"(b.y));
}

// smem layout (floats):
//  A: [buf][wr(2)][kstep(4)][mtile(4)][lane(32)][4]   -> 4096 per buf
//  B: [buf][wc(4)][kstep(4)][ntile(4)][lane(32)][2]   -> 4096 per buf
#define A_OFF(buf, wr, ks, mt, lane) (((((buf)*2 + (wr))*4 + (ks))*4 + (mt))*128 + (lane)*4)
#define B_OFF(buf, wc, ks, nt, lane) (((((buf)*4 + (wc))*4 + (ks))*4 + (nt))*64 + (lane)*2)

__global__ __launch_bounds__(256)
void wgemm_tf32_kernel(const float* __restrict__ A, const float* __restrict__ B,
                       float* __restrict__ C, int M, long sA, long sB, long sC)
{
    extern __shared__ float sm[];
    float* As = sm;            // 8192 floats (2 bufs)
    float* Bs = sm + 8192;     // 8192 floats (2 bufs)

    A += (long)blockIdx.z * sA;
    B += (long)blockIdx.z * sB;
    C += (long)blockIdx.z * sC;

    const int m0 = blockIdx.y * 128;
    const int n0 = blockIdx.x * 128;
    const int tid = threadIdx.x;
    const int wid = tid >> 5;
    const int lane = tid & 31;
    const int wr = wid >> 2;
    const int wc = wid & 3;

    float4 acc[4][4];
    #pragma unroll
    for (int i = 0; i < 4; i++)
        #pragma unroll
        for (int j = 0; j < 4; j++) acc[i][j] = make_float4(0.f, 0.f, 0.f, 0.f);

    float regA[16];
    float regB[16];

    // ---- gmem load of chunk kc into regs ----
    auto load_chunk = [&](int kc) {
        const int k0 = kc * 32;
        #pragma unroll
        for (int p = 0; p < 4; p++) {
            const int i = p * 256 + tid;
            const int row = i >> 3;
            const int kq = (i & 7) * 4;
            const int gm = m0 + row;
            float4 v = make_float4(0.f, 0.f, 0.f, 0.f);
            if (gm < M)
                v = *reinterpret_cast<const float4*>(A + (long)gm * WG_K + (k0 + kq));
            *reinterpret_cast<float4*>(&regA[p * 4]) = v;
        }
        #pragma unroll
        for (int p = 0; p < 4; p++) {
            const int i = p * 256 + tid;
            const int kr = i >> 5;
            const int nq = (i & 31) * 4;
            *reinterpret_cast<float4*>(&regB[p * 4]) =
                *reinterpret_cast<const float4*>(B + (long)(k0 + kr) * WG_N + (n0 + nq));
        }
    };

    // ---- scatter regs into fragment-ordered smem buffer ----
    auto scatter = [&](int buf) {
        #pragma unroll
        for (int p = 0; p < 4; p++) {
            const int i = p * 256 + tid;
            const int row = i >> 3;
            const int kq = (i & 7) * 4;
            const int wrL = row >> 6;
            const int m6 = row & 63;
            const int mt = m6 >> 4;
            const int r = m6 & 15;
            #pragma unroll
            for (int j = 0; j < 4; j++) {
                const int kk = (kq + j) & 7;
                const int ks = (kq + j) >> 3;
                const int areg = (r >> 3) + ((kk >> 2) << 1);
                const int ln = (r & 7) * 4 + (kk & 3);
                As[A_OFF(buf, wrL, ks, mt, ln) + areg] = to_tf32(regA[p * 4 + j]);
            }
        }
        #pragma unroll
        for (int p = 0; p < 4; p++) {
            const int i = p * 256 + tid;
            const int kr = i >> 5;
            const int nq = (i & 31) * 4;
            const int kk = kr & 7;
            const int ks = kr >> 3;
            const int breg = kk >> 2;
            const int tig = kk & 3;
            #pragma unroll
            for (int j = 0; j < 4; j++) {
                const int n = nq + j;
                const int wcL = n >> 5;
                const int n5 = n & 31;
                const int nt = n5 >> 3;
                const int gid = n5 & 7;
                Bs[B_OFF(buf, wcL, ks, nt, gid * 4 + tig) + breg] = to_tf32(regB[p * 4 + j]);
            }
        }
    };

    load_chunk(0);
    scatter(0);
    __syncthreads();

    for (int kc = 0; kc < WG_NKC; kc++) {
        const int buf = kc & 1;
        const bool more = (kc + 1 < WG_NKC);
        if (more) load_chunk(kc + 1);

        #pragma unroll
        for (int s = 0; s < 4; s++) {
            uint4 afr[4];
            uint2 bfr[4];
            #pragma unroll
            for (int mt = 0; mt < 4; mt++)
                afr[mt] = *reinterpret_cast<const uint4*>(&As[A_OFF(buf, wr, s, mt, lane)]);
            #pragma unroll
            for (int nt = 0; nt < 4; nt++)
                bfr[nt] = *reinterpret_cast<const uint2*>(&Bs[B_OFF(buf, wc, s, nt, lane)]);
            #pragma unroll
            for (int mt = 0; mt < 4; mt++)
                #pragma unroll
                for (int nt = 0; nt < 4; nt++)
                    mma_tf32(acc[mt][nt], afr[mt], bfr[nt]);
        }

        if (more) scatter(buf ^ 1);
        __syncthreads();
    }

    // ---- epilogue ----
    const int gid = lane >> 2;
    const int tig = lane & 3;
    #pragma unroll
    for (int mt = 0; mt < 4; mt++) {
        const int r0 = m0 + wr * 64 + mt * 16 + gid;
        const int r1 = r0 + 8;
        #pragma unroll
        for (int nt = 0; nt < 4; nt++) {
            const int col = n0 + wc * 32 + nt * 8 + tig * 2;
            const float4 c = acc[mt][nt];
            if (r0 < M) {
                float2 v0 = make_float2(c.x, c.y);
                *reinterpret_cast<float2*>(C + (long)r0 * WG_N + col) = v0;
            }
            if (r1 < M) {
                float2 v1 = make_float2(c.z, c.w);
                *reinterpret_cast<float2*>(C + (long)r1 * WG_N + col) = v1;
            }
        }
    }
}

// ---------------- instance norm + LeakyReLU + spatial re-center (in place) ----------------
__global__ __launch_bounds__(256)
void instnorm_kernel(float* __restrict__ F)
{
    __shared__ float sh[HW];
    __shared__ float red[8];
    const int c = blockIdx.x;
    const int n = blockIdx.y;
    float* row = F + ((long)n * C_MID + c) * HW;
    const int tid = threadIdx.x;

    float s = 0.f, s2 = 0.f;
    for (int i = tid; i < HW; i += 256) {
        const float v = row[i];
        sh[i] = v; s += v; s2 += v * v;
    }
    s  = blk_sum(s,  red);
    s2 = blk_sum(s2, red);
    const float mean = s * (1.f / HW);
    const float var  = s2 * (1.f / HW) - mean * mean;
    const float inv  = rsqrtf(var + 1e-5f);

    float s3 = 0.f;
    for (int i = tid; i < HW; i += 256) {
        float v = (sh[i] - mean) * inv;
        v = (v >= 0.f) ? v : 0.2f * v;
        sh[i] = v;
        s3 += v;
    }
    s3 = blk_sum(s3, red);
    const float mean2 = s3 * (1.f / HW);
    for (int i = tid; i < HW; i += 256)
        row[i] = sh[i] - mean2;
}

// ---------------- per-spatial-column L2 normalize over channels (in place) ----------------
__global__ __launch_bounds__(256)
void l2norm_kernel(float* __restrict__ F)
{
    const int l = blockIdx.x * 256 + threadIdx.x;
    const int n = blockIdx.y;
    float* base = F + (long)n * C_MID * HW + l;
    float s = 0.f;
    #pragma unroll 8
    for (int c = 0; c < C_MID; c++) {
        const float v = base[(long)c * HW];
        s += v * v;
    }
    const float inv = rsqrtf(s);
    #pragma unroll 8
    for (int c = 0; c < C_MID; c++)
        base[(long)c * HW] *= inv;
}

// ---------------- in-place row softmax ----------------
__global__ __launch_bounds__(256)
void softmax_kernel(float* __restrict__ E)
{
    __shared__ float sh[HW];
    __shared__ float red[8];
    float* row = E + ((long)blockIdx.y * HW + blockIdx.x) * HW;
    const int tid = threadIdx.x;

    float mx = -3.4e38f;
    for (int i = tid; i < HW; i += 256) {
        const float v = row[i];
        sh[i] = v;
        mx = fmaxf(mx, v);
    }
    mx = blk_max(mx, red);

    float s = 0.f;
    for (int i = tid; i < HW; i += 256) {
        const float e = __expf(sh[i] - mx);
        sh[i] = e;
        s += e;
    }
    s = blk_sum(s, red);
    const float inv = 1.f / s;
    for (int i = tid; i < HW; i += 256)
        row[i] = sh[i] * inv;
}

// ---------------- launch ----------------
extern "C" void kernel_launch(void* const* d_in, const int* in_sizes, int n_in,
                              void* d_out, int out_size)
{
    const float* fa    = (const float*)d_in[0];
    const float* fb    = (const float*)d_in[1];
    const float* a_raw = (const float*)d_in[2];
    const float* b_raw = (const float*)d_in[3];
    const float* Wa    = (const float*)d_in[4];
    const float* ba    = (const float*)d_in[5];
    const float* Wb    = (const float*)d_in[6];
    const float* bb    = (const float*)d_in[7];
    float* out = (float*)d_out;

    float *pfa, *pfb;
    cudaGetSymbolAddress((void**)&pfa, g_fa);
    cudaGetSymbolAddress((void**)&pfb, g_fb);

    static bool attr_done = false;
    if (!attr_done) {
        cudaFuncSetAttribute(wgemm_tf32_kernel,
                             cudaFuncAttributeMaxDynamicSharedMemorySize, 65536);
        attr_done = true;
    }

    const long CORR = (long)HW * HW;
    float* corr_ab = out;
    float* corr_ba = out + (long)N_B * CORR;
    float* a_warp  = out + 2L * N_B * CORR;
    float* b_warp  = a_warp + (long)N_B * C_IN * HW;

    const dim3 blk(256);

    // 1) 1x1 conv (fp32 — precision-critical, feeds exp(100*x) downstream)
    {
        dim3 g(HW / BN, (C_MID + BM - 1) / BM, N_B);
        sgemm_kernel<false, 1><<<g, blk>>>(Wa, fa, ba, pfa, C_MID, HW, C_IN,
                                           0L, (long)C_IN * HW, (long)C_MID * HW, 0.f);
        sgemm_kernel<false, 1><<<g, blk>>>(Wb, fb, bb, pfb, C_MID, HW, C_IN,
                                           0L, (long)C_IN * HW, (long)C_MID * HW, 0.f);
    }

    // 2) InstanceNorm + LeakyReLU + spatial re-center
    {
        dim3 g(C_MID, N_B);
        instnorm_kernel<<<g, blk>>>(pfa);
        instnorm_kernel<<<g, blk>>>(pfb);
    }

    // 3) per-column L2 normalize
    {
        dim3 g(HW / 256, N_B);
        l2norm_kernel<<<g, blk>>>(pfa);
        l2norm_kernel<<<g, blk>>>(pfb);
    }

    // 4) energy GEMMs (fp32 — precision-critical), straight into corr regions (x100)
    {
        dim3 g(HW / BN, HW / BM, N_B);
        sgemm_kernel<true, 2><<<g, blk>>>(pfb, pfa, nullptr, corr_ab, HW, HW, C_MID,
                                          (long)C_MID * HW, (long)C_MID * HW, CORR, 100.f);
        sgemm_kernel<true, 2><<<g, blk>>>(pfa, pfb, nullptr, corr_ba, HW, HW, C_MID,
                                          (long)C_MID * HW, (long)C_MID * HW, CORR, 100.f);
    }

    // 5) in-place softmax over all corr rows
    {
        dim3 g(HW, 2 * N_B);
        softmax_kernel<<<g, blk>>>(out);
    }

    // 6) warp GEMMs on tensor cores (tf32)
    {
        dim3 g(HW / 128, (C_IN + 127) / 128, N_B);
        wgemm_tf32_kernel<<<g, blk, 65536>>>(b_raw, corr_ab, b_warp, C_IN,
                                             (long)C_IN * HW, CORR, (long)C_IN * HW);
        wgemm_tf32_kernel<<<g, blk, 65536>>>(a_raw, corr_ba, a_warp, C_IN,
                                             (long)C_IN * HW, CORR, (long)C_IN * HW);
    }
}

// round 3
// speedup vs baseline: 1.7927x; 1.5929x over previous
#include <cuda_runtime.h>
#include <math.h>
#include <stdint.h>

// ---------------- problem constants ----------------
#define N_B   2
#define C_IN  1088
#define C_MID 136
#define HW    4096

// scratch
__device__ __align__(16) float g_fa[N_B * C_MID * HW];
__device__ __align__(16) float g_fb[N_B * C_MID * HW];
__device__ __align__(16) float g_ta[N_B * C_IN * HW];   // tf32-rounded a_raw
__device__ __align__(16) float g_tb[N_B * C_IN * HW];   // tf32-rounded b_raw

typedef unsigned long long ull;

// ---------------- helpers ----------------
__device__ __forceinline__ ull pack2(float x, float y) {
    ull r; asm("mov.b64 %0, {%1, %2};" : "=l"(r) : "f"(x), "f"(y)); return r;
}
__device__ __forceinline__ float2 unpack2(ull v) {
    float2 f; asm("mov.b64 {%0, %1}, %2;" : "=f"(f.x), "=f"(f.y) : "l"(v)); return f;
}
__device__ __forceinline__ void ffma2u(ull& d, ull a, ull b) {
    asm("fma.rn.f32x2 %0, %1, %2, %0;" : "+l"(d) : "l"(a), "l"(b));
}
__device__ __forceinline__ uint32_t cvt_tf32(float f) {
    uint32_t u; asm("cvt.rna.tf32.f32 %0, %1;" : "=r"(u) : "f"(f)); return u;
}
__device__ __forceinline__ void cp16(uint32_t dst, const void* src, uint32_t sz) {
    asm volatile("cp.async.ca.shared.global [%0], [%1], 16, %2;"
                 :: "r"(dst), "l"(src), "r"(sz));
}
__device__ __forceinline__ void cp_commit() { asm volatile("cp.async.commit_group;"); }
__device__ __forceinline__ void cp_wait0()  { asm volatile("cp.async.wait_group 0;"); }

__device__ __forceinline__ float blk_sum(float v, float* red) {
    const int tid = threadIdx.x;
    #pragma unroll
    for (int o = 16; o > 0; o >>= 1) v += __shfl_down_sync(0xffffffffu, v, o);
    if ((tid & 31) == 0) red[tid >> 5] = v;
    __syncthreads();
    if (tid < 32) {
        v = (tid < 8) ? red[tid] : 0.f;
        #pragma unroll
        for (int o = 4; o > 0; o >>= 1) v += __shfl_down_sync(0xffffffffu, v, o);
        if (tid == 0) red[0] = v;
    }
    __syncthreads();
    v = red[0];
    __syncthreads();
    return v;
}

__device__ __forceinline__ float blk_max(float v, float* red) {
    const int tid = threadIdx.x;
    #pragma unroll
    for (int o = 16; o > 0; o >>= 1) v = fmaxf(v, __shfl_down_sync(0xffffffffu, v, o));
    if ((tid & 31) == 0) red[tid >> 5] = v;
    __syncthreads();
    if (tid < 32) {
        v = (tid < 8) ? red[tid] : -3.4e38f;
        #pragma unroll
        for (int o = 4; o > 0; o >>= 1) v = fmaxf(v, __shfl_down_sync(0xffffffffu, v, o));
        if (tid == 0) red[0] = v;
    }
    __syncthreads();
    v = red[0];
    __syncthreads();
    return v;
}

// ---------------- fp32 SIMT GEMM with packed f32x2 FMA ----------------
// C[m,n] = sum_k opA[m,k]*B[k,n]  (+bias[m] if EPI==1, *alpha if EPI==2)
// Pointer pair selected by blockIdx.z>>1; batch = blockIdx.z&1.
#define BM 128
#define BN 128
#define BK 8
#define TM 8
#define TN 8

template<bool TRANS_A, int EPI>
__global__ __launch_bounds__(256, 2)
void sgemm2_kernel(const float* __restrict__ A0, const float* __restrict__ A1,
                   const float* __restrict__ B0, const float* __restrict__ B1,
                   const float* __restrict__ bs0, const float* __restrict__ bs1,
                   float* __restrict__ C0, float* __restrict__ C1,
                   int M, int N, int K, long sA, long sB, long sC, float alpha)
{
    __shared__ float As[BK][BM];
    __shared__ float Bs[BK][BN];

    const int sel = blockIdx.z >> 1, bat = blockIdx.z & 1;
    const float* A = (sel ? A1 : A0) + (long)bat * sA;
    const float* B = (sel ? B1 : B0) + (long)bat * sB;
    const float* bias = sel ? bs1 : bs0;
    float* C = (sel ? C1 : C0) + (long)bat * sC;

    const int m0 = blockIdx.y * BM;
    const int n0 = blockIdx.x * BN;
    const int tid = threadIdx.x;
    const int tx = tid & 15;
    const int ty = tid >> 4;
    const int idx = tid * 4;

    ull acc[4][TN];   // row pairs x cols
    #pragma unroll
    for (int i = 0; i < 4; i++)
        #pragma unroll
        for (int j = 0; j < TN; j++) acc[i][j] = 0ULL;

    for (int k0 = 0; k0 < K; k0 += BK) {
        if (TRANS_A) {
            const int kk = idx / BM;
            const int mm = idx % BM;
            const float4 v = *reinterpret_cast<const float4*>(
                A + (long)(k0 + kk) * M + (m0 + mm));
            *reinterpret_cast<float4*>(&As[kk][mm]) = v;
        } else {
            const int mm = idx / BK;
            const int kk = idx % BK;
            const int row = m0 + mm;
            float4 v = make_float4(0.f, 0.f, 0.f, 0.f);
            if (row < M)
                v = *reinterpret_cast<const float4*>(A + (long)row * K + (k0 + kk));
            As[kk + 0][mm] = v.x;
            As[kk + 1][mm] = v.y;
            As[kk + 2][mm] = v.z;
            As[kk + 3][mm] = v.w;
        }
        {
            const int kk = idx / BN;
            const int nn = idx % BN;
            const float4 v = *reinterpret_cast<const float4*>(
                B + (long)(k0 + kk) * N + (n0 + nn));
            *reinterpret_cast<float4*>(&Bs[kk][nn]) = v;
        }
        __syncthreads();

        #pragma unroll
        for (int kk = 0; kk < BK; kk++) {
            const ulonglong2 a01 = *reinterpret_cast<const ulonglong2*>(&As[kk][ty * TM]);
            const ulonglong2 a23 = *reinterpret_cast<const ulonglong2*>(&As[kk][ty * TM + 4]);
            const float4 rb0 = *reinterpret_cast<const float4*>(&Bs[kk][tx * TN]);
            const float4 rb1 = *reinterpret_cast<const float4*>(&Bs[kk][tx * TN + 4]);
            ull ap[4] = { a01.x, a01.y, a23.x, a23.y };
            float rb[8] = { rb0.x, rb0.y, rb0.z, rb0.w, rb1.x, rb1.y, rb1.z, rb1.w };
            #pragma unroll
            for (int j = 0; j < TN; j++) {
                const ull bb = pack2(rb[j], rb[j]);
                #pragma unroll
                for (int i = 0; i < 4; i++)
                    ffma2u(acc[i][j], ap[i], bb);
            }
        }
        __syncthreads();
    }

    #pragma unroll
    for (int i2 = 0; i2 < 4; i2++) {
        float2 lo[TN];
        #pragma unroll
        for (int j = 0; j < TN; j++) lo[j] = unpack2(acc[i2][j]);
        #pragma unroll
        for (int half = 0; half < 2; half++) {
            const int row = m0 + ty * TM + 2 * i2 + half;
            if (row >= M) continue;
            const float bv = (EPI == 1) ? bias[row] : 0.f;
            float r[TN];
            #pragma unroll
            for (int j = 0; j < TN; j++) r[j] = half ? lo[j].y : lo[j].x;
            #pragma unroll
            for (int j = 0; j < TN; j += 4) {
                float4 v = make_float4(r[j], r[j+1], r[j+2], r[j+3]);
                if (EPI == 1) { v.x += bv; v.y += bv; v.z += bv; v.w += bv; }
                if (EPI == 2) { v.x *= alpha; v.y *= alpha; v.z *= alpha; v.w *= alpha; }
                *reinterpret_cast<float4*>(C + (long)row * N + n0 + tx * TN + j) = v;
            }
        }
    }
}

// ---------------- tf32 tensor-core GEMM (warp stage), cp.async pipeline ----------------
// C[M,4096] = A[M,4096] @ B[4096,4096]; A pre-rounded to tf32 bits; B fp32 (cvt on load).
#define WG_N 4096
#define WG_K 4096
#define WG_NC (WG_K / 32)
#define WA_ROW 36
#define WB_ROW 136
#define WA_SZ (128 * WA_ROW)          // 4608 floats
#define WB_SZ (32 * WB_ROW)           // 4352 floats
#define WSTAGE (WA_SZ + WB_SZ)        // 8960 floats per stage
#define WSMEM_BYTES (2 * WSTAGE * 4)  // 71680

__device__ __forceinline__ void mma_tf32(float4& c, const uint32_t a[4], const uint32_t b[2]) {
    asm volatile(
        "mma.sync.aligned.m16n8k8.row.col.f32.tf32.tf32.f32 "
        "{%0,%1,%2,%3},{%4,%5,%6,%7},{%8,%9},{%0,%1,%2,%3};"
        : "+f"(c.x), "+f"(c.y), "+f"(c.z), "+f"(c.w)
        : "r"(a[0]), "r"(a[1]), "r"(a[2]), "r"(a[3]), "r"(b[0]), "r"(b[1]));
}

__global__ __launch_bounds__(256)
void wgemm_tf32_kernel(const float* __restrict__ TA0, const float* __restrict__ TA1,
                       const float* __restrict__ TB0, const float* __restrict__ TB1,
                       float* __restrict__ TC0, float* __restrict__ TC1,
                       int M, long sA, long sB, long sC)
{
    extern __shared__ float sm[];
    const int sel = blockIdx.z >> 1, bat = blockIdx.z & 1;
    const float* A = (sel ? TA1 : TA0) + (long)bat * sA;
    const float* B = (sel ? TB1 : TB0) + (long)bat * sB;
    float* C = (sel ? TC1 : TC0) + (long)bat * sC;

    const int m0 = blockIdx.y * 128;
    const int n0 = blockIdx.x * 128;
    const int tid = threadIdx.x;
    const int wid = tid >> 5;
    const int lane = tid & 31;
    const int wr = wid >> 2;          // 0..1 : 64 rows
    const int wc = wid & 3;           // 0..3 : 32 cols
    const int r = lane >> 2;
    const int c = lane & 3;

    const uint32_t smem_base = (uint32_t)__cvta_generic_to_shared(sm);

    // per-thread copy assignments (constant across chunks)
    const float* srcA[4]; uint32_t dstA[4]; uint32_t szA[4];
    const float* srcB[4]; uint32_t dstB[4];
    #pragma unroll
    for (int p = 0; p < 4; p++) {
        const int g = p * 256 + tid;
        const int row = g >> 3, q = g & 7;
        srcA[p] = A + (long)(m0 + row) * WG_K + q * 4;
        dstA[p] = (uint32_t)((row * WA_ROW + q * 4) * 4);
        szA[p] = (m0 + row < M) ? 16u : 0u;
        const int kr = g >> 5, qb = g & 31;
        srcB[p] = B + (long)kr * WG_N + n0 + qb * 4;
        dstB[p] = (uint32_t)((WA_SZ + kr * WB_ROW + qb * 4) * 4);
    }

    auto load_stage = [&](int kc, int st) {
        const uint32_t sb = smem_base + (uint32_t)(st * WSTAGE * 4);
        const long offA = (long)kc * 32;
        const long offB = (long)kc * 32 * WG_N;
        #pragma unroll
        for (int p = 0; p < 4; p++) cp16(sb + dstA[p], srcA[p] + offA, szA[p]);
        #pragma unroll
        for (int p = 0; p < 4; p++) cp16(sb + dstB[p], srcB[p] + offB, 16u);
        cp_commit();
    };

    float4 acc[4][4];
    #pragma unroll
    for (int i = 0; i < 4; i++)
        #pragma unroll
        for (int j = 0; j < 4; j++) acc[i][j] = make_float4(0.f, 0.f, 0.f, 0.f);

    load_stage(0, 0);

    for (int kc = 0; kc < WG_NC; kc++) {
        const int st = kc & 1;
        cp_wait0();
        __syncthreads();
        if (kc + 1 < WG_NC) load_stage(kc + 1, st ^ 1);

        const float* Asm = sm + st * WSTAGE;
        const float* Bsm = Asm + WA_SZ;
        #pragma unroll
        for (int s = 0; s < 4; s++) {
            uint32_t a[4][4], b[4][2];
            #pragma unroll
            for (int mt = 0; mt < 4; mt++) {
                const float* ap = Asm + (wr * 64 + mt * 16 + r) * WA_ROW + s * 8 + c;
                a[mt][0] = __float_as_uint(ap[0]);              // A pre-rounded: bits are tf32
                a[mt][1] = __float_as_uint(ap[8 * WA_ROW]);
                a[mt][2] = __float_as_uint(ap[4]);
                a[mt][3] = __float_as_uint(ap[8 * WA_ROW + 4]);
            }
            #pragma unroll
            for (int nt = 0; nt < 4; nt++) {
                const float* bp = Bsm + (s * 8 + c) * WB_ROW + wc * 32 + nt * 8 + r;
                b[nt][0] = cvt_tf32(bp[0]);
                b[nt][1] = cvt_tf32(bp[4 * WB_ROW]);
            }
            #pragma unroll
            for (int mt = 0; mt < 4; mt++)
                #pragma unroll
                for (int nt = 0; nt < 4; nt++)
                    mma_tf32(acc[mt][nt], a[mt], b[nt]);
        }
        __syncthreads();
    }

    const int gid = lane >> 2;
    const int tig = lane & 3;
    #pragma unroll
    for (int mt = 0; mt < 4; mt++) {
        const int r0 = m0 + wr * 64 + mt * 16 + gid;
        const int r1 = r0 + 8;
        #pragma unroll
        for (int nt = 0; nt < 4; nt++) {
            const int col = n0 + wc * 32 + nt * 8 + tig * 2;
            const float4 cc = acc[mt][nt];
            if (r0 < M)
                *reinterpret_cast<float2*>(C + (long)r0 * WG_N + col) = make_float2(cc.x, cc.y);
            if (r1 < M)
                *reinterpret_cast<float2*>(C + (long)r1 * WG_N + col) = make_float2(cc.z, cc.w);
        }
    }
}

// ---------------- tf32 pre-round of raw tensors ----------------
__global__ __launch_bounds__(256)
void round_tf32_kernel(const float* __restrict__ a, const float* __restrict__ b,
                       float* __restrict__ oa, float* __restrict__ ob)
{
    const float* src = blockIdx.z ? b : a;
    float* dst = blockIdx.z ? ob : oa;
    const long i = ((long)blockIdx.x * 256 + threadIdx.x) * 4;
    float4 v = *reinterpret_cast<const float4*>(src + i);
    v.x = __uint_as_float(cvt_tf32(v.x));
    v.y = __uint_as_float(cvt_tf32(v.y));
    v.z = __uint_as_float(cvt_tf32(v.z));
    v.w = __uint_as_float(cvt_tf32(v.w));
    *reinterpret_cast<float4*>(dst + i) = v;
}

// ---------------- instance norm + LeakyReLU + re-center (both tensors) ----------------
__global__ __launch_bounds__(256)
void instnorm_kernel(float* __restrict__ Fa, float* __restrict__ Fb)
{
    __shared__ float sh[HW];
    __shared__ float red[8];
    float* F = blockIdx.z ? Fb : Fa;
    float* row = F + ((long)blockIdx.y * C_MID + blockIdx.x) * HW;
    const int tid = threadIdx.x;

    float s = 0.f, s2 = 0.f;
    for (int i = tid; i < HW; i += 256) {
        const float v = row[i];
        sh[i] = v; s += v; s2 += v * v;
    }
    s  = blk_sum(s,  red);
    s2 = blk_sum(s2, red);
    const float mean = s * (1.f / HW);
    const float var  = s2 * (1.f / HW) - mean * mean;
    const float inv  = rsqrtf(var + 1e-5f);

    float s3 = 0.f;
    for (int i = tid; i < HW; i += 256) {
        float v = (sh[i] - mean) * inv;
        v = (v >= 0.f) ? v : 0.2f * v;
        sh[i] = v;
        s3 += v;
    }
    s3 = blk_sum(s3, red);
    const float mean2 = s3 * (1.f / HW);
    for (int i = tid; i < HW; i += 256)
        row[i] = sh[i] - mean2;
}

// ---------------- per-column L2 normalize (both tensors) ----------------
__global__ __launch_bounds__(256)
void l2norm_kernel(float* __restrict__ Fa, float* __restrict__ Fb)
{
    float* F = blockIdx.z ? Fb : Fa;
    const int l = blockIdx.x * 256 + threadIdx.x;
    float* base = F + (long)blockIdx.y * C_MID * HW + l;
    float s = 0.f;
    #pragma unroll 8
    for (int cc = 0; cc < C_MID; cc++) {
        const float v = base[(long)cc * HW];
        s += v * v;
    }
    const float inv = rsqrtf(s);
    #pragma unroll 8
    for (int cc = 0; cc < C_MID; cc++)
        base[(long)cc * HW] *= inv;
}

// ---------------- in-place row softmax ----------------
__global__ __launch_bounds__(256)
void softmax_kernel(float* __restrict__ E)
{
    __shared__ float sh[HW];
    __shared__ float red[8];
    float* row = E + ((long)blockIdx.y * HW + blockIdx.x) * HW;
    const int tid = threadIdx.x;

    float mx = -3.4e38f;
    for (int i = tid; i < HW; i += 256) {
        const float v = row[i];
        sh[i] = v;
        mx = fmaxf(mx, v);
    }
    mx = blk_max(mx, red);

    float s = 0.f;
    for (int i = tid; i < HW; i += 256) {
        const float e = __expf(sh[i] - mx);
        sh[i] = e;
        s += e;
    }
    s = blk_sum(s, red);
    const float inv = 1.f / s;
    for (int i = tid; i < HW; i += 256)
        row[i] = sh[i] * inv;
}

// ---------------- launch ----------------
extern "C" void kernel_launch(void* const* d_in, const int* in_sizes, int n_in,
                              void* d_out, int out_size)
{
    const float* fa    = (const float*)d_in[0];
    const float* fb    = (const float*)d_in[1];
    const float* a_raw = (const float*)d_in[2];
    const float* b_raw = (const float*)d_in[3];
    const float* Wa    = (const float*)d_in[4];
    const float* ba    = (const float*)d_in[5];
    const float* Wb    = (const float*)d_in[6];
    const float* bb    = (const float*)d_in[7];
    float* out = (float*)d_out;

    float *pfa, *pfb, *pta, *ptb;
    cudaGetSymbolAddress((void**)&pfa, g_fa);
    cudaGetSymbolAddress((void**)&pfb, g_fb);
    cudaGetSymbolAddress((void**)&pta, g_ta);
    cudaGetSymbolAddress((void**)&ptb, g_tb);

    cudaFuncSetAttribute(wgemm_tf32_kernel,
                         cudaFuncAttributeMaxDynamicSharedMemorySize, WSMEM_BYTES);

    const long CORR = (long)HW * HW;
    float* corr_ab = out;
    float* corr_ba = out + (long)N_B * CORR;
    float* a_warp  = out + 2L * N_B * CORR;
    float* b_warp  = a_warp + (long)N_B * C_IN * HW;

    const dim3 blk(256);
    const long sMID = (long)C_MID * HW;
    const long sIN  = (long)C_IN * HW;

    // 1) 1x1 conv (fp32 f32x2), both tensors + batches in one launch
    {
        dim3 g(HW / BN, (C_MID + BM - 1) / BM, 4);
        sgemm2_kernel<false, 1><<<g, blk>>>(Wa, Wb, fa, fb, ba, bb, pfa, pfb,
                                            C_MID, HW, C_IN, 0L, sIN, sMID, 0.f);
    }
    // 2) InstanceNorm + LeakyReLU + re-center
    {
        dim3 g(C_MID, N_B, 2);
        instnorm_kernel<<<g, blk>>>(pfa, pfb);
    }
    // 3) per-column L2 normalize
    {
        dim3 g(HW / 256, N_B, 2);
        l2norm_kernel<<<g, blk>>>(pfa, pfb);
    }
    // 4) energy GEMMs (fp32 f32x2), both directions + batches, x100 into corr regions
    {
        dim3 g(HW / BN, HW / BM, 4);
        sgemm2_kernel<true, 2><<<g, blk>>>(pfb, pfa, pfa, pfb, nullptr, nullptr,
                                           corr_ab, corr_ba,
                                           HW, HW, C_MID, sMID, sMID, CORR, 100.f);
    }
    // 5) in-place softmax over all corr rows
    {
        dim3 g(HW, 2 * N_B);
        softmax_kernel<<<g, blk>>>(out);
    }
    // 6) pre-round raw tensors to tf32
    {
        dim3 g((unsigned)((long)N_B * C_IN * HW / 4 / 256), 1, 2);
        round_tf32_kernel<<<g, blk>>>(a_raw, b_raw, pta, ptb);
    }
    // 7) warp GEMMs on tensor cores (tf32, cp.async pipeline)
    {
        dim3 g(HW / 128, (C_IN + 127) / 128, 4);
        wgemm_tf32_kernel<<<g, blk, WSMEM_BYTES>>>(ptb, pta, corr_ab, corr_ba,
                                                   b_warp, a_warp,
                                                   C_IN, sIN, CORR, sIN);
    }
}

// round 4
// speedup vs baseline: 2.7851x; 1.5536x over previous
#include <cuda_runtime.h>
#include <math.h>
#include <stdint.h>

// ---------------- problem constants ----------------
#define N_B   2
#define C_IN  1088
#define C_MID 136
#define HW    4096

// scratch
__device__ __align__(16) float g_fa[N_B * C_MID * HW];
__device__ __align__(16) float g_fb[N_B * C_MID * HW];
__device__ __align__(16) float g_ta[N_B * C_IN * HW];   // tf32-rounded a_raw
__device__ __align__(16) float g_tb[N_B * C_IN * HW];   // tf32-rounded b_raw

typedef unsigned long long ull;

// ---------------- helpers ----------------
__device__ __forceinline__ ull pack2(float x, float y) {
    ull r; asm("mov.b64 %0, {%1, %2};" : "=l"(r) : "f"(x), "f"(y)); return r;
}
__device__ __forceinline__ float2 unpack2(ull v) {
    float2 f; asm("mov.b64 {%0, %1}, %2;" : "=f"(f.x), "=f"(f.y) : "l"(v)); return f;
}
__device__ __forceinline__ void ffma2u(ull& d, ull a, ull b) {
    asm("fma.rn.f32x2 %0, %1, %2, %0;" : "+l"(d) : "l"(a), "l"(b));
}
__device__ __forceinline__ uint32_t cvt_tf32(float f) {
    uint32_t u; asm("cvt.rna.tf32.f32 %0, %1;" : "=r"(u) : "f"(f)); return u;
}
__device__ __forceinline__ void cp16(uint32_t dst, const void* src, uint32_t sz) {
    asm volatile("cp.async.ca.shared.global [%0], [%1], 16, %2;"
                 :: "r"(dst), "l"(src), "r"(sz));
}
__device__ __forceinline__ void cp_commit() { asm volatile("cp.async.commit_group;"); }
__device__ __forceinline__ void cp_wait0()  { asm volatile("cp.async.wait_group 0;"); }

__device__ __forceinline__ float blk_sum(float v, float* red) {
    const int tid = threadIdx.x;
    #pragma unroll
    for (int o = 16; o > 0; o >>= 1) v += __shfl_down_sync(0xffffffffu, v, o);
    if ((tid & 31) == 0) red[tid >> 5] = v;
    __syncthreads();
    if (tid < 32) {
        v = (tid < 8) ? red[tid] : 0.f;
        #pragma unroll
        for (int o = 4; o > 0; o >>= 1) v += __shfl_down_sync(0xffffffffu, v, o);
        if (tid == 0) red[0] = v;
    }
    __syncthreads();
    v = red[0];
    __syncthreads();
    return v;
}

__device__ __forceinline__ float blk_max(float v, float* red) {
    const int tid = threadIdx.x;
    #pragma unroll
    for (int o = 16; o > 0; o >>= 1) v = fmaxf(v, __shfl_down_sync(0xffffffffu, v, o));
    if ((tid & 31) == 0) red[tid >> 5] = v;
    __syncthreads();
    if (tid < 32) {
        v = (tid < 8) ? red[tid] : -3.4e38f;
        #pragma unroll
        for (int o = 4; o > 0; o >>= 1) v = fmaxf(v, __shfl_down_sync(0xffffffffu, v, o));
        if (tid == 0) red[0] = v;
    }
    __syncthreads();
    v = red[0];
    __syncthreads();
    return v;
}

// ---------------- fp32 SIMT GEMM with packed f32x2 FMA ----------------
// C[m,n] = sum_k opA[m,k]*B[k,n]  (+bias[m] if EPI==1, *alpha if EPI==2)
// Pointer pair selected by blockIdx.z>>1; batch = blockIdx.z&1.
#define BM 128
#define BN 128
#define BK 8
#define TM 8
#define TN 8

template<bool TRANS_A, int EPI>
__global__ __launch_bounds__(256, 2)
void sgemm2_kernel(const float* __restrict__ A0, const float* __restrict__ A1,
                   const float* __restrict__ B0, const float* __restrict__ B1,
                   const float* __restrict__ bs0, const float* __restrict__ bs1,
                   float* __restrict__ C0, float* __restrict__ C1,
                   int M, int N, int K, long sA, long sB, long sC, float alpha)
{
    __shared__ float As[BK][BM];
    __shared__ float Bs[BK][BN];

    const int sel = blockIdx.z >> 1, bat = blockIdx.z & 1;
    const float* A = (sel ? A1 : A0) + (long)bat * sA;
    const float* B = (sel ? B1 : B0) + (long)bat * sB;
    const float* bias = sel ? bs1 : bs0;
    float* C = (sel ? C1 : C0) + (long)bat * sC;

    const int m0 = blockIdx.y * BM;
    const int n0 = blockIdx.x * BN;
    const int tid = threadIdx.x;
    const int tx = tid & 15;
    const int ty = tid >> 4;
    const int idx = tid * 4;

    ull acc[4][TN];   // row pairs x cols
    #pragma unroll
    for (int i = 0; i < 4; i++)
        #pragma unroll
        for (int j = 0; j < TN; j++) acc[i][j] = 0ULL;

    for (int k0 = 0; k0 < K; k0 += BK) {
        if (TRANS_A) {
            const int kk = idx / BM;
            const int mm = idx % BM;
            const float4 v = *reinterpret_cast<const float4*>(
                A + (long)(k0 + kk) * M + (m0 + mm));
            *reinterpret_cast<float4*>(&As[kk][mm]) = v;
        } else {
            const int mm = idx / BK;
            const int kk = idx % BK;
            const int row = m0 + mm;
            float4 v = make_float4(0.f, 0.f, 0.f, 0.f);
            if (row < M)
                v = *reinterpret_cast<const float4*>(A + (long)row * K + (k0 + kk));
            As[kk + 0][mm] = v.x;
            As[kk + 1][mm] = v.y;
            As[kk + 2][mm] = v.z;
            As[kk + 3][mm] = v.w;
        }
        {
            const int kk = idx / BN;
            const int nn = idx % BN;
            const float4 v = *reinterpret_cast<const float4*>(
                B + (long)(k0 + kk) * N + (n0 + nn));
            *reinterpret_cast<float4*>(&Bs[kk][nn]) = v;
        }
        __syncthreads();

        #pragma unroll
        for (int kk = 0; kk < BK; kk++) {
            const ulonglong2 a01 = *reinterpret_cast<const ulonglong2*>(&As[kk][ty * TM]);
            const ulonglong2 a23 = *reinterpret_cast<const ulonglong2*>(&As[kk][ty * TM + 4]);
            const float4 rb0 = *reinterpret_cast<const float4*>(&Bs[kk][tx * TN]);
            const float4 rb1 = *reinterpret_cast<const float4*>(&Bs[kk][tx * TN + 4]);
            ull ap[4] = { a01.x, a01.y, a23.x, a23.y };
            float rb[8] = { rb0.x, rb0.y, rb0.z, rb0.w, rb1.x, rb1.y, rb1.z, rb1.w };
            #pragma unroll
            for (int j = 0; j < TN; j++) {
                const ull bb = pack2(rb[j], rb[j]);
                #pragma unroll
                for (int i = 0; i < 4; i++)
                    ffma2u(acc[i][j], ap[i], bb);
            }
        }
        __syncthreads();
    }

    #pragma unroll
    for (int i2 = 0; i2 < 4; i2++) {
        float2 lo[TN];
        #pragma unroll
        for (int j = 0; j < TN; j++) lo[j] = unpack2(acc[i2][j]);
        #pragma unroll
        for (int half = 0; half < 2; half++) {
            const int row = m0 + ty * TM + 2 * i2 + half;
            if (row >= M) continue;
            const float bv = (EPI == 1) ? bias[row] : 0.f;
            float r[TN];
            #pragma unroll
            for (int j = 0; j < TN; j++) r[j] = half ? lo[j].y : lo[j].x;
            #pragma unroll
            for (int j = 0; j < TN; j += 4) {
                float4 v = make_float4(r[j], r[j+1], r[j+2], r[j+3]);
                if (EPI == 1) { v.x += bv; v.y += bv; v.z += bv; v.w += bv; }
                if (EPI == 2) { v.x *= alpha; v.y *= alpha; v.z *= alpha; v.w *= alpha; }
                *reinterpret_cast<float4*>(C + (long)row * N + n0 + tx * TN + j) = v;
            }
        }
    }
}

// ---------------- tf32 tensor-core GEMM (warp stage), cp.async pipeline ----------------
// C[M,4096] = A[M,4096] @ B[4096,4096]; A pre-rounded to tf32 bits; B fp32 (cvt on load).
#define WG_N 4096
#define WG_K 4096
#define WG_NC (WG_K / 32)
#define WA_ROW 36
#define WB_ROW 136
#define WA_SZ (128 * WA_ROW)          // 4608 floats
#define WB_SZ (32 * WB_ROW)           // 4352 floats
#define WSTAGE (WA_SZ + WB_SZ)        // 8960 floats per stage
#define WSMEM_BYTES (2 * WSTAGE * 4)  // 71680

__device__ __forceinline__ void mma_tf32(float4& c, const uint32_t a[4], const uint32_t b[2]) {
    asm volatile(
        "mma.sync.aligned.m16n8k8.row.col.f32.tf32.tf32.f32 "
        "{%0,%1,%2,%3},{%4,%5,%6,%7},{%8,%9},{%0,%1,%2,%3};"
        : "+f"(c.x), "+f"(c.y), "+f"(c.z), "+f"(c.w)
        : "r"(a[0]), "r"(a[1]), "r"(a[2]), "r"(a[3]), "r"(b[0]), "r"(b[1]));
}

__global__ __launch_bounds__(256)
void wgemm_tf32_kernel(const float* __restrict__ TA0, const float* __restrict__ TA1,
                       const float* __restrict__ TB0, const float* __restrict__ TB1,
                       float* __restrict__ TC0, float* __restrict__ TC1,
                       int M, long sA, long sB, long sC)
{
    extern __shared__ float sm[];
    const int sel = blockIdx.z >> 1, bat = blockIdx.z & 1;
    const float* A = (sel ? TA1 : TA0) + (long)bat * sA;
    const float* B = (sel ? TB1 : TB0) + (long)bat * sB;
    float* C = (sel ? TC1 : TC0) + (long)bat * sC;

    const int m0 = blockIdx.y * 128;
    const int n0 = blockIdx.x * 128;
    const int tid = threadIdx.x;
    const int wid = tid >> 5;
    const int lane = tid & 31;
    const int wr = wid >> 2;          // 0..1 : 64 rows
    const int wc = wid & 3;           // 0..3 : 32 cols
    const int r = lane >> 2;
    const int c = lane & 3;

    const uint32_t smem_base = (uint32_t)__cvta_generic_to_shared(sm);

    // per-thread copy assignments (constant across chunks)
    const float* srcA[4]; uint32_t dstA[4]; uint32_t szA[4];
    const float* srcB[4]; uint32_t dstB[4];
    #pragma unroll
    for (int p = 0; p < 4; p++) {
        const int g = p * 256 + tid;
        const int row = g >> 3, q = g & 7;
        srcA[p] = A + (long)(m0 + row) * WG_K + q * 4;
        dstA[p] = (uint32_t)((row * WA_ROW + q * 4) * 4);
        szA[p] = (m0 + row < M) ? 16u : 0u;
        const int kr = g >> 5, qb = g & 31;
        srcB[p] = B + (long)kr * WG_N + n0 + qb * 4;
        dstB[p] = (uint32_t)((WA_SZ + kr * WB_ROW + qb * 4) * 4);
    }

    auto load_stage = [&](int kc, int st) {
        const uint32_t sb = smem_base + (uint32_t)(st * WSTAGE * 4);
        const long offA = (long)kc * 32;
        const long offB = (long)kc * 32 * WG_N;
        #pragma unroll
        for (int p = 0; p < 4; p++) cp16(sb + dstA[p], srcA[p] + offA, szA[p]);
        #pragma unroll
        for (int p = 0; p < 4; p++) cp16(sb + dstB[p], srcB[p] + offB, 16u);
        cp_commit();
    };

    float4 acc[4][4];
    #pragma unroll
    for (int i = 0; i < 4; i++)
        #pragma unroll
        for (int j = 0; j < 4; j++) acc[i][j] = make_float4(0.f, 0.f, 0.f, 0.f);

    load_stage(0, 0);

    for (int kc = 0; kc < WG_NC; kc++) {
        const int st = kc & 1;
        cp_wait0();
        __syncthreads();
        if (kc + 1 < WG_NC) load_stage(kc + 1, st ^ 1);

        const float* Asm = sm + st * WSTAGE;
        const float* Bsm = Asm + WA_SZ;
        #pragma unroll
        for (int s = 0; s < 4; s++) {
            uint32_t a[4][4], b[4][2];
            #pragma unroll
            for (int mt = 0; mt < 4; mt++) {
                const float* ap = Asm + (wr * 64 + mt * 16 + r) * WA_ROW + s * 8 + c;
                a[mt][0] = __float_as_uint(ap[0]);              // A pre-rounded: bits are tf32
                a[mt][1] = __float_as_uint(ap[8 * WA_ROW]);
                a[mt][2] = __float_as_uint(ap[4]);
                a[mt][3] = __float_as_uint(ap[8 * WA_ROW + 4]);
            }
            #pragma unroll
            for (int nt = 0; nt < 4; nt++) {
                const float* bp = Bsm + (s * 8 + c) * WB_ROW + wc * 32 + nt * 8 + r;
                b[nt][0] = cvt_tf32(bp[0]);
                b[nt][1] = cvt_tf32(bp[4 * WB_ROW]);
            }
            #pragma unroll
            for (int mt = 0; mt < 4; mt++)
                #pragma unroll
                for (int nt = 0; nt < 4; nt++)
                    mma_tf32(acc[mt][nt], a[mt], b[nt]);
        }
        __syncthreads();
    }

    const int gid = lane >> 2;
    const int tig = lane & 3;
    #pragma unroll
    for (int mt = 0; mt < 4; mt++) {
        const int r0 = m0 + wr * 64 + mt * 16 + gid;
        const int r1 = r0 + 8;
        #pragma unroll
        for (int nt = 0; nt < 4; nt++) {
            const int col = n0 + wc * 32 + nt * 8 + tig * 2;
            const float4 cc = acc[mt][nt];
            if (r0 < M)
                *reinterpret_cast<float2*>(C + (long)r0 * WG_N + col) = make_float2(cc.x, cc.y);
            if (r1 < M)
                *reinterpret_cast<float2*>(C + (long)r1 * WG_N + col) = make_float2(cc.z, cc.w);
        }
    }
}

// ---------------- tf32 pre-round of raw tensors ----------------
__global__ __launch_bounds__(256)
void round_tf32_kernel(const float* __restrict__ a, const float* __restrict__ b,
                       float* __restrict__ oa, float* __restrict__ ob)
{
    const float* src = blockIdx.z ? b : a;
    float* dst = blockIdx.z ? ob : oa;
    const long i = ((long)blockIdx.x * 256 + threadIdx.x) * 4;
    float4 v = *reinterpret_cast<const float4*>(src + i);
    v.x = __uint_as_float(cvt_tf32(v.x));
    v.y = __uint_as_float(cvt_tf32(v.y));
    v.z = __uint_as_float(cvt_tf32(v.z));
    v.w = __uint_as_float(cvt_tf32(v.w));
    *reinterpret_cast<float4*>(dst + i) = v;
}

// ---------------- instance norm + LeakyReLU + re-center (both tensors) ----------------
__global__ __launch_bounds__(256)
void instnorm_kernel(float* __restrict__ Fa, float* __restrict__ Fb)
{
    __shared__ float sh[HW];
    __shared__ float red[8];
    float* F = blockIdx.z ? Fb : Fa;
    float* row = F + ((long)blockIdx.y * C_MID + blockIdx.x) * HW;
    const int tid = threadIdx.x;

    float s = 0.f, s2 = 0.f;
    for (int i = tid; i < HW; i += 256) {
        const float v = row[i];
        sh[i] = v; s += v; s2 += v * v;
    }
    s  = blk_sum(s,  red);
    s2 = blk_sum(s2, red);
    const float mean = s * (1.f / HW);
    const float var  = s2 * (1.f / HW) - mean * mean;
    const float inv  = rsqrtf(var + 1e-5f);

    float s3 = 0.f;
    for (int i = tid; i < HW; i += 256) {
        float v = (sh[i] - mean) * inv;
        v = (v >= 0.f) ? v : 0.2f * v;
        sh[i] = v;
        s3 += v;
    }
    s3 = blk_sum(s3, red);
    const float mean2 = s3 * (1.f / HW);
    for (int i = tid; i < HW; i += 256)
        row[i] = sh[i] - mean2;
}

// ---------------- per-column L2 normalize (both tensors) ----------------
__global__ __launch_bounds__(256)
void l2norm_kernel(float* __restrict__ Fa, float* __restrict__ Fb)
{
    float* F = blockIdx.z ? Fb : Fa;
    const int l = blockIdx.x * 256 + threadIdx.x;
    float* base = F + (long)blockIdx.y * C_MID * HW + l;
    float s = 0.f;
    #pragma unroll 8
    for (int cc = 0; cc < C_MID; cc++) {
        const float v = base[(long)cc * HW];
        s += v * v;
    }
    const float inv = rsqrtf(s);
    #pragma unroll 8
    for (int cc = 0; cc < C_MID; cc++)
        base[(long)cc * HW] *= inv;
}

// ---------------- in-place row softmax ----------------
__global__ __launch_bounds__(256)
void softmax_kernel(float* __restrict__ E)
{
    __shared__ float sh[HW];
    __shared__ float red[8];
    float* row = E + ((long)blockIdx.y * HW + blockIdx.x) * HW;
    const int tid = threadIdx.x;

    float mx = -3.4e38f;
    for (int i = tid; i < HW; i += 256) {
        const float v = row[i];
        sh[i] = v;
        mx = fmaxf(mx, v);
    }
    mx = blk_max(mx, red);

    float s = 0.f;
    for (int i = tid; i < HW; i += 256) {
        const float e = __expf(sh[i] - mx);
        sh[i] = e;
        s += e;
    }
    s = blk_sum(s, red);
    const float inv = 1.f / s;
    for (int i = tid; i < HW; i += 256)
        row[i] = sh[i] * inv;
}

// ---------------- launch ----------------
extern "C" void kernel_launch(void* const* d_in, const int* in_sizes, int n_in,
                              void* d_out, int out_size)
{
    const float* fa    = (const float*)d_in[0];
    const float* fb    = (const float*)d_in[1];
    const float* a_raw = (const float*)d_in[2];
    const float* b_raw = (const float*)d_in[3];
    const float* Wa    = (const float*)d_in[4];
    const float* ba    = (const float*)d_in[5];
    const float* Wb    = (const float*)d_in[6];
    const float* bb    = (const float*)d_in[7];
    float* out = (float*)d_out;

    float *pfa, *pfb, *pta, *ptb;
    cudaGetSymbolAddress((void**)&pfa, g_fa);
    cudaGetSymbolAddress((void**)&pfb, g_fb);
    cudaGetSymbolAddress((void**)&pta, g_ta);
    cudaGetSymbolAddress((void**)&ptb, g_tb);

    cudaFuncSetAttribute(wgemm_tf32_kernel,
                         cudaFuncAttributeMaxDynamicSharedMemorySize, WSMEM_BYTES);

    const long CORR = (long)HW * HW;
    float* corr_ab = out;
    float* corr_ba = out + (long)N_B * CORR;
    float* a_warp  = out + 2L * N_B * CORR;
    float* b_warp  = a_warp + (long)N_B * C_IN * HW;

    const dim3 blk(256);
    const long sMID = (long)C_MID * HW;
    const long sIN  = (long)C_IN * HW;

    // 1) 1x1 conv (fp32 f32x2), both tensors + batches in one launch
    {
        dim3 g(HW / BN, (C_MID + BM - 1) / BM, 4);
        sgemm2_kernel<false, 1><<<g, blk>>>(Wa, Wb, fa, fb, ba, bb, pfa, pfb,
                                            C_MID, HW, C_IN, 0L, sIN, sMID, 0.f);
    }
    // 2) InstanceNorm + LeakyReLU + re-center
    {
        dim3 g(C_MID, N_B, 2);
        instnorm_kernel<<<g, blk>>>(pfa, pfb);
    }
    // 3) per-column L2 normalize
    {
        dim3 g(HW / 256, N_B, 2);
        l2norm_kernel<<<g, blk>>>(pfa, pfb);
    }
    // 4) energy GEMMs (fp32 f32x2), both directions + batches, x100 into corr regions
    {
        dim3 g(HW / BN, HW / BM, 4);
        sgemm2_kernel<true, 2><<<g, blk>>>(pfb, pfa, pfa, pfb, nullptr, nullptr,
                                           corr_ab, corr_ba,
                                           HW, HW, C_MID, sMID, sMID, CORR, 100.f);
    }
    // 5) in-place softmax over all corr rows
    {
        dim3 g(HW, 2 * N_B);
        softmax_kernel<<<g, blk>>>(out);
    }
    // 6) pre-round raw tensors to tf32
    {
        dim3 g((unsigned)((long)N_B * C_IN * HW / 4 / 256), 1, 2);
        round_tf32_kernel<<<g, blk>>>(a_raw, b_raw, pta, ptb);
    }
    // 7) warp GEMMs on tensor cores (tf32, cp.async pipeline)
    {
        dim3 g(HW / 128, (C_IN + 127) / 128, 4);
        wgemm_tf32_kernel<<<g, blk, WSMEM_BYTES>>>(ptb, pta, corr_ab, corr_ba,
                                                   b_warp, a_warp,
                                                   C_IN, sIN, CORR, sIN);
    }
}